// round 16
// baseline (speedup 1.0000x reference)
#include <cuda_runtime.h>
#include <math.h>

// s = sum_i R[i] * ||Z[i,:]||^2 ; out = 1 - exp(-exp(s))
// Z: [N,128] fp32 row-major (256 MB), R: [N] fp32 (2 MB). HBM-bound reduction.
//
// 4 exact waves of small CTAs (4864 = 152 SMs x 8 slots x 4). Waves >= 2 are
// dispatched by the HW scheduler on-demand ("wave>=2 work-steal"), so fast SMs
// absorb more CTAs and the L2-die finish-time spread is balanced in hardware --
// no atomics, no barriers in the work path. Hot loop identical to R15.

#define NBLOCKS  4864                   // 152 x 8 x 4 : four exact waves
#define NTHREADS 256

static __device__ float        g_partials[NBLOCKS];
static __device__ unsigned int g_arrive = 0;   // wraps back to 0 each launch

__global__ __launch_bounds__(NTHREADS, 8) void bp_fused_kernel(
    const float* __restrict__ Z, const float* __restrict__ R, int nrows,
    float* __restrict__ out)
{
    const float4* __restrict__ Z4 = reinterpret_cast<const float4*>(Z);
    const int total4 = nrows * 32;                    // 32 float4 per 128-wide row
    const int stride = gridDim.x * blockDim.x;        // threads in grid
    const int tid    = blockIdx.x * blockDim.x + threadIdx.x;

    float a0 = 0.f, a1 = 0.f, a2 = 0.f, a3 = 0.f;

    int j = tid;
    // Unroll x4, independent accumulators -> 4 front-batched LDG.128 + 4 R loads
    // in flight per trip. Regs stay <=32 so 8 CTAs/SM remain resident.
    for (; j + 3 * stride < total4; j += 4 * stride) {
        float4 v0 = Z4[j];
        float4 v1 = Z4[j +     stride];
        float4 v2 = Z4[j + 2 * stride];
        float4 v3 = Z4[j + 3 * stride];
        float  r0 = __ldg(&R[(j             ) >> 5]);
        float  r1 = __ldg(&R[(j +     stride) >> 5]);
        float  r2 = __ldg(&R[(j + 2 * stride) >> 5]);
        float  r3 = __ldg(&R[(j + 3 * stride) >> 5]);
        a0 = fmaf(v0.x*v0.x + v0.y*v0.y + v0.z*v0.z + v0.w*v0.w, r0, a0);
        a1 = fmaf(v1.x*v1.x + v1.y*v1.y + v1.z*v1.z + v1.w*v1.w, r1, a1);
        a2 = fmaf(v2.x*v2.x + v2.y*v2.y + v2.z*v2.z + v2.w*v2.w, r2, a2);
        a3 = fmaf(v3.x*v3.x + v3.y*v3.y + v3.z*v3.z + v3.w*v3.w, r3, a3);
    }
    for (; j < total4; j += stride) {
        float4 v = Z4[j];
        float  r = __ldg(&R[j >> 5]);
        a0 = fmaf(v.x*v.x + v.y*v.y + v.z*v.z + v.w*v.w, r, a0);
    }

    float acc = (a0 + a1) + (a2 + a3);

    // warp reduce
    #pragma unroll
    for (int o = 16; o > 0; o >>= 1)
        acc += __shfl_xor_sync(0xffffffffu, acc, o);

    __shared__ float smem[NTHREADS / 32];
    if ((threadIdx.x & 31) == 0) smem[threadIdx.x >> 5] = acc;
    __syncthreads();

    if (threadIdx.x < 32) {
        float v = (threadIdx.x < NTHREADS / 32) ? smem[threadIdx.x] : 0.f;
        #pragma unroll
        for (int o = (NTHREADS / 32) / 2; o > 0; o >>= 1)
            v += __shfl_xor_sync(0xffffffffu, v, o);
        if (threadIdx.x == 0) g_partials[blockIdx.x] = v;
    }

    // ---- last block finalizes (deterministic: fixed-order sum of partials) ----
    __shared__ bool is_last;
    __threadfence();                                  // partials visible grid-wide
    if (threadIdx.x == 0) {
        unsigned int prev = atomicInc(&g_arrive, NBLOCKS - 1); // wraps -> auto-reset
        is_last = (prev == NBLOCKS - 1);
    }
    __syncthreads();
    if (!is_last) return;

    double dacc = 0.0;
    for (int i = threadIdx.x; i < NBLOCKS; i += NTHREADS)
        dacc += (double)g_partials[i];

    #pragma unroll
    for (int o = 16; o > 0; o >>= 1)
        dacc += __shfl_xor_sync(0xffffffffu, dacc, o);

    __shared__ double dsmem[NTHREADS / 32];
    if ((threadIdx.x & 31) == 0) dsmem[threadIdx.x >> 5] = dacc;
    __syncthreads();

    if (threadIdx.x == 0) {
        double s = 0.0;
        #pragma unroll
        for (int w = 0; w < NTHREADS / 32; w++) s += dsmem[w];
        double lam = exp(s);
        out[0] = (float)(1.0 - exp(-lam));
    }
}

extern "C" void kernel_launch(void* const* d_in, const int* in_sizes, int n_in,
                              void* d_out, int out_size)
{
    const float* a0 = (const float*)d_in[0];
    const float* a1 = (const float*)d_in[1];
    const float* Z; const float* R; int nrows;
    if (in_sizes[0] >= in_sizes[1]) { Z = a0; R = a1; nrows = in_sizes[1]; }
    else                            { Z = a1; R = a0; nrows = in_sizes[0]; }

    bp_fused_kernel<<<NBLOCKS, NTHREADS>>>(Z, R, nrows, (float*)d_out);
}

// round 17
// speedup vs baseline: 1.2089x; 1.2089x over previous
#include <cuda_runtime.h>
#include <math.h>

// s = sum_i R[i] * ||Z[i,:]||^2 ; out = 1 - exp(-exp(s))
// Z: [N,128] fp32 row-major (256 MB), R: [N] fp32 (2 MB). HBM-bound reduction.
//
// One static resident wave (measured best: 1 wave 74% DRAM vs 4 waves 63%,
// steal variants worse). This round trades occupancy for per-thread MLP:
// unroll x8 with 8 independent accumulators (8 front-batched LDG.128 per trip),
// 64-reg budget, 4 CTAs/SM -> grid 608 = 152x4, still exactly one wave.

#define NBLOCKS  608                    // 152 SMs x 4 CTAs -- one full wave
#define NTHREADS 256

static __device__ float        g_partials[NBLOCKS];
static __device__ unsigned int g_arrive = 0;   // wraps back to 0 each launch

__global__ __launch_bounds__(NTHREADS, 4) void bp_fused_kernel(
    const float* __restrict__ Z, const float* __restrict__ R, int nrows,
    float* __restrict__ out)
{
    const float4* __restrict__ Z4 = reinterpret_cast<const float4*>(Z);
    const int total4 = nrows * 32;                    // 32 float4 per 128-wide row
    const int stride = gridDim.x * blockDim.x;        // threads in grid
    const int tid    = blockIdx.x * blockDim.x + threadIdx.x;

    float a0 = 0.f, a1 = 0.f, a2 = 0.f, a3 = 0.f;
    float a4 = 0.f, a5 = 0.f, a6 = 0.f, a7 = 0.f;

    int j = tid;
    // Unroll x8: 8 independent LDG.128 + 8 R loads batched per trip (MLP_p1=8).
    for (; j + 7 * stride < total4; j += 8 * stride) {
        float4 v0 = Z4[j];
        float4 v1 = Z4[j +     stride];
        float4 v2 = Z4[j + 2 * stride];
        float4 v3 = Z4[j + 3 * stride];
        float4 v4 = Z4[j + 4 * stride];
        float4 v5 = Z4[j + 5 * stride];
        float4 v6 = Z4[j + 6 * stride];
        float4 v7 = Z4[j + 7 * stride];
        float  r0 = __ldg(&R[(j             ) >> 5]);
        float  r1 = __ldg(&R[(j +     stride) >> 5]);
        float  r2 = __ldg(&R[(j + 2 * stride) >> 5]);
        float  r3 = __ldg(&R[(j + 3 * stride) >> 5]);
        float  r4 = __ldg(&R[(j + 4 * stride) >> 5]);
        float  r5 = __ldg(&R[(j + 5 * stride) >> 5]);
        float  r6 = __ldg(&R[(j + 6 * stride) >> 5]);
        float  r7 = __ldg(&R[(j + 7 * stride) >> 5]);
        a0 = fmaf(v0.x*v0.x + v0.y*v0.y + v0.z*v0.z + v0.w*v0.w, r0, a0);
        a1 = fmaf(v1.x*v1.x + v1.y*v1.y + v1.z*v1.z + v1.w*v1.w, r1, a1);
        a2 = fmaf(v2.x*v2.x + v2.y*v2.y + v2.z*v2.z + v2.w*v2.w, r2, a2);
        a3 = fmaf(v3.x*v3.x + v3.y*v3.y + v3.z*v3.z + v3.w*v3.w, r3, a3);
        a4 = fmaf(v4.x*v4.x + v4.y*v4.y + v4.z*v4.z + v4.w*v4.w, r4, a4);
        a5 = fmaf(v5.x*v5.x + v5.y*v5.y + v5.z*v5.z + v5.w*v5.w, r5, a5);
        a6 = fmaf(v6.x*v6.x + v6.y*v6.y + v6.z*v6.z + v6.w*v6.w, r6, a6);
        a7 = fmaf(v7.x*v7.x + v7.y*v7.y + v7.z*v7.z + v7.w*v7.w, r7, a7);
    }
    for (; j < total4; j += stride) {
        float4 v = Z4[j];
        float  r = __ldg(&R[j >> 5]);
        a0 = fmaf(v.x*v.x + v.y*v.y + v.z*v.z + v.w*v.w, r, a0);
    }

    float acc = ((a0 + a1) + (a2 + a3)) + ((a4 + a5) + (a6 + a7));

    // warp reduce
    #pragma unroll
    for (int o = 16; o > 0; o >>= 1)
        acc += __shfl_xor_sync(0xffffffffu, acc, o);

    __shared__ float smem[NTHREADS / 32];
    if ((threadIdx.x & 31) == 0) smem[threadIdx.x >> 5] = acc;
    __syncthreads();

    if (threadIdx.x < 32) {
        float v = (threadIdx.x < NTHREADS / 32) ? smem[threadIdx.x] : 0.f;
        #pragma unroll
        for (int o = (NTHREADS / 32) / 2; o > 0; o >>= 1)
            v += __shfl_xor_sync(0xffffffffu, v, o);
        if (threadIdx.x == 0) g_partials[blockIdx.x] = v;
    }

    // ---- last block finalizes (deterministic: fixed-order sum of partials) ----
    __shared__ bool is_last;
    __threadfence();                                  // partials visible grid-wide
    if (threadIdx.x == 0) {
        unsigned int prev = atomicInc(&g_arrive, NBLOCKS - 1); // wraps -> auto-reset
        is_last = (prev == NBLOCKS - 1);
    }
    __syncthreads();
    if (!is_last) return;

    double dacc = 0.0;
    for (int i = threadIdx.x; i < NBLOCKS; i += NTHREADS)
        dacc += (double)g_partials[i];

    #pragma unroll
    for (int o = 16; o > 0; o >>= 1)
        dacc += __shfl_xor_sync(0xffffffffu, dacc, o);

    __shared__ double dsmem[NTHREADS / 32];
    if ((threadIdx.x & 31) == 0) dsmem[threadIdx.x >> 5] = dacc;
    __syncthreads();

    if (threadIdx.x == 0) {
        double s = 0.0;
        #pragma unroll
        for (int w = 0; w < NTHREADS / 32; w++) s += dsmem[w];
        double lam = exp(s);
        out[0] = (float)(1.0 - exp(-lam));
    }
}

extern "C" void kernel_launch(void* const* d_in, const int* in_sizes, int n_in,
                              void* d_out, int out_size)
{
    const float* a0 = (const float*)d_in[0];
    const float* a1 = (const float*)d_in[1];
    const float* Z; const float* R; int nrows;
    if (in_sizes[0] >= in_sizes[1]) { Z = a0; R = a1; nrows = in_sizes[1]; }
    else                            { Z = a1; R = a0; nrows = in_sizes[0]; }

    bp_fused_kernel<<<NBLOCKS, NTHREADS>>>(Z, R, nrows, (float*)d_out);
}